// round 9
// baseline (speedup 1.0000x reference)
#include <cuda_runtime.h>
#include <cuda_bf16.h>

// WMAE: out = sum_{i,j} w[j] * |t1[i,j] - t2[i,j]| / n_sample
// t1, t2: (n_sample, 3) fp32, row-major. w = {300, 1, 200}.
// Pure HBM-bound streaming reduction: ~100.7 MB read -> scalar.

#define W0 300.0f
#define W1   1.0f
#define W2 200.0f

__global__ void wmae_zero_kernel(float* out) {
    out[0] = 0.0f;
}

// Each "group" = 12 contiguous floats = 3 float4. Since 12 % 3 == 0, the
// per-lane weight pattern within a group is compile-time fixed:
//   v0: (w0,w1,w2,w0)  v1: (w1,w2,w0,w1)  v2: (w2,w0,w1,w2)
__global__ void __launch_bounds__(256)
wmae_kernel(const float4* __restrict__ a4,
            const float4* __restrict__ b4,
            const float*  __restrict__ a,
            const float*  __restrict__ b,
            float* __restrict__ out,
            int ngroups, int n_total, float inv_n)
{
    float s = 0.0f;

    const int stride = gridDim.x * blockDim.x;
    for (int g = blockIdx.x * blockDim.x + threadIdx.x; g < ngroups; g += stride) {
        const int base = g * 3;
        float4 a0 = a4[base + 0];
        float4 a1 = a4[base + 1];
        float4 a2 = a4[base + 2];
        float4 b0 = b4[base + 0];
        float4 b1 = b4[base + 1];
        float4 b2 = b4[base + 2];

        s += W0 * fabsf(a0.x - b0.x);
        s += W1 * fabsf(a0.y - b0.y);
        s += W2 * fabsf(a0.z - b0.z);
        s += W0 * fabsf(a0.w - b0.w);

        s += W1 * fabsf(a1.x - b1.x);
        s += W2 * fabsf(a1.y - b1.y);
        s += W0 * fabsf(a1.z - b1.z);
        s += W1 * fabsf(a1.w - b1.w);

        s += W2 * fabsf(a2.x - b2.x);
        s += W0 * fabsf(a2.y - b2.y);
        s += W1 * fabsf(a2.z - b2.z);
        s += W2 * fabsf(a2.w - b2.w);
    }

    // Scalar tail (n_total % 12 != 0) — empty for this problem's shape,
    // kept for generality across seeds/shape variants.
    const float w3[3] = {W0, W1, W2};
    for (int i = ngroups * 12 + blockIdx.x * blockDim.x + threadIdx.x;
         i < n_total; i += stride) {
        s += w3[i % 3] * fabsf(a[i] - b[i]);
    }

    // Warp reduction
    #pragma unroll
    for (int off = 16; off > 0; off >>= 1)
        s += __shfl_xor_sync(0xFFFFFFFFu, s, off);

    // Block reduction
    __shared__ float warp_sums[8];
    const int lane = threadIdx.x & 31;
    const int wid  = threadIdx.x >> 5;
    if (lane == 0) warp_sums[wid] = s;
    __syncthreads();

    if (wid == 0) {
        s = (lane < (blockDim.x >> 5)) ? warp_sums[lane] : 0.0f;
        #pragma unroll
        for (int off = 4; off > 0; off >>= 1)
            s += __shfl_xor_sync(0xFFFFFFFFu, s, off);
        if (lane == 0)
            atomicAdd(out, s * inv_n);
    }
}

extern "C" void kernel_launch(void* const* d_in, const int* in_sizes, int n_in,
                              void* d_out, int out_size)
{
    const float* t1 = (const float*)d_in[0];
    const float* t2 = (const float*)d_in[1];
    float* out = (float*)d_out;

    const int n_total  = in_sizes[0];          // 12,582,912
    const int ngroups  = n_total / 12;         // 1,048,576
    const int n_sample = n_total / 3;          // 4,194,304
    const float inv_n  = 1.0f / (float)n_sample;

    wmae_zero_kernel<<<1, 1>>>(out);

    const int threads = 256;
    int blocks = (ngroups + threads - 1) / threads;
    if (blocks > 1184) blocks = 1184;          // 148 SMs * 8 blocks
    if (blocks < 1) blocks = 1;

    wmae_kernel<<<blocks, threads>>>(
        (const float4*)t1, (const float4*)t2,
        t1, t2, out, ngroups, n_total, inv_n);
}